// round 16
// baseline (speedup 1.0000x reference)
#include <cuda_runtime.h>
#include <cuda_bf16.h>
#include <cuda_fp16.h>
#include <cstdint>

// Problem constants
constexpr int B   = 4;
constexpr int S   = 2048;
constexpr int HID = 512;
constexpr int NH  = 8;
constexpr int DH  = 64;
constexpr int M   = B * S;       // 8192

// Scratch (device globals — no runtime allocation allowed)
__device__ __half g_wh16[4][HID * HID], g_wl16[4][HID * HID];
__device__ __half g_q16[M * HID], g_k16[M * HID], g_v16[M * HID];
__device__ __half g_o16[M * HID];

// ---------------------------------------------------------------------------
// mma.sync / ldmatrix / cp.async helpers (plain sm_80+ PTX)
// ---------------------------------------------------------------------------
__device__ __forceinline__ uint32_t smem_u32(const void* p) {
  uint32_t a;
  asm("{ .reg .u64 t; cvta.to.shared.u64 t, %1; cvt.u32.u64 %0, t; }"
      : "=r"(a) : "l"(p));
  return a;
}

#define LDMX4(r0, r1, r2, r3, addr)                                       \
  asm volatile(                                                           \
      "ldmatrix.sync.aligned.m8n8.x4.shared.b16 {%0,%1,%2,%3}, [%4];"     \
      : "=r"(r0), "=r"(r1), "=r"(r2), "=r"(r3) : "r"(addr))

#define LDMX4T(r0, r1, r2, r3, addr)                                      \
  asm volatile(                                                           \
      "ldmatrix.sync.aligned.m8n8.x4.trans.shared.b16 {%0,%1,%2,%3}, [%4];" \
      : "=r"(r0), "=r"(r1), "=r"(r2), "=r"(r3) : "r"(addr))

#define CP_ASYNC16(dst, src)                                              \
  asm volatile("cp.async.cg.shared.global [%0], [%1], 16;" ::             \
                   "r"(dst), "l"(src))
#define CP_COMMIT() asm volatile("cp.async.commit_group;" ::: "memory")
#define CP_WAIT0() asm volatile("cp.async.wait_group 0;" ::: "memory")
#define CP_WAIT1() asm volatile("cp.async.wait_group 1;" ::: "memory")

__device__ __forceinline__ void mma_f16(float& c0, float& c1, float& c2,
                                        float& c3, uint32_t a0, uint32_t a1,
                                        uint32_t a2, uint32_t a3,
                                        uint32_t b0, uint32_t b1) {
  asm volatile(
      "mma.sync.aligned.m16n8k16.row.col.f32.f16.f16.f32 "
      "{%0,%1,%2,%3}, {%4,%5,%6,%7}, {%8,%9}, {%0,%1,%2,%3};"
      : "+f"(c0), "+f"(c1), "+f"(c2), "+f"(c3)
      : "r"(a0), "r"(a1), "r"(a2), "r"(a3), "r"(b0), "r"(b1));
}

__device__ __forceinline__ uint32_t pack_f16(float a, float b) {
  __half2 t = __floats2half2_rn(a, b);
  return *(uint32_t*)&t;
}

// Fast exp2 on the (idle) FMA pipe: degree-5 Taylor of 2^f on [0,1),
// exponent assembled via integer bit-ops. Truncation error <= 1.5e-4
// (below the fp16-P quantization of 2.4e-4). Input clamped at -126 so
// masked -1e30 scores map to ~2^-126 ~= 0, same as exp2f underflow.
__device__ __forceinline__ float fexp2(float x) {
  x = fmaxf(x, -126.0f);
  float n = floorf(x);
  float f = x - n;
  float p = 1.3333558e-3f;                 // ln2^5/120
  p = fmaf(p, f, 9.6181291e-3f);           // ln2^4/24
  p = fmaf(p, f, 5.5504109e-2f);           // ln2^3/6
  p = fmaf(p, f, 2.4022651e-1f);           // ln2^2/2
  p = fmaf(p, f, 6.9314718e-1f);           // ln2
  p = fmaf(p, f, 1.0f);
  int e = (int)n;
  float s = __int_as_float((e + 127) << 23);
  return p * s;
}

// ---------------------------------------------------------------------------
// Weight split: fp32 -> fp16 hi + fp16 lo (2-term; residual ~2^-22).
// ---------------------------------------------------------------------------
struct SplitBatch {
  const float* src[4];
  __half* hi[4];
  __half* lo[4];
};

__global__ __launch_bounds__(256) void split_batch_kernel(SplitBatch sb,
                                                          int n4) {
  int i = blockIdx.x * blockDim.x + threadIdx.x;
  if (i >= n4) return;
  int z = blockIdx.y;
  float4 v = ((const float4*)sb.src[z])[i];
  float hx = __half2float(__float2half_rn(v.x));
  float hy = __half2float(__float2half_rn(v.y));
  float hz = __half2float(__float2half_rn(v.z));
  float hw = __half2float(__float2half_rn(v.w));
  uint2 ho, lw;
  ho.x = pack_f16(v.x, v.y);
  ho.y = pack_f16(v.z, v.w);
  lw.x = pack_f16(v.x - hx, v.y - hy);
  lw.y = pack_f16(v.z - hz, v.w - hw);
  ((uint2*)sb.hi[z])[i] = ho;
  ((uint2*)sb.lo[z])[i] = lw;
}

// ---------------------------------------------------------------------------
// HMMA fp16x2 GEMM-NT: C = A16 @ (Wh + Wl)^T — 2 MMA terms per k16.
// ---------------------------------------------------------------------------
constexpr int RS = 72;                    // smem row stride in halfs (144 B)
constexpr int TILE_BYTES = 128 * RS * 2;  // 18432 per tile
constexpr int SA16 = 0;                   // A: 1 tile
constexpr int SW_BASE = TILE_BYTES;       // 18432
constexpr int W_STG = 2 * TILE_BYTES;     // Wh+Wl per stage
constexpr int GEMM_SMEM = SW_BASE + 2 * W_STG;  // 92160 (x2 CTAs fits)

struct GemmBatch {
  const float* af[3];                 // AFP32 inputs
  const __half* a16;                  // !AFP32 input (out-proj A = O fp16)
  const __half* wh[3];
  const __half* wl[3];
  __half* c16[3];                     // F16OUT outputs
  float* c;                           // !F16OUT output
  const int* vlens;                   // valid_lens (skip for z=1,2); null ok
};

template <bool AFP32, bool F16OUT>
__global__ __launch_bounds__(256, 2) void gemm_tc_hmma(GemmBatch p) {
  extern __shared__ __align__(128) char smem[];
  const uint32_t sb = smem_u32(smem);
  const int t = threadIdx.x;
  const int wid = t >> 5, l = t & 31;
  const int wm = wid >> 2;
  const int wn = wid & 3;
  const int m0 = blockIdx.y * 128;
  const int n0 = blockIdx.x * 128;
  const int z = blockIdx.z;

  if (AFP32 && z != 0) {
    int vl = p.vlens[m0 >> 11];       // batch = m0 / S (S = 2048)
    if ((m0 & (S - 1)) >= vl) return;
  }

  const __half* Wh = p.wh[z];
  const __half* Wl = p.wl[z];

  auto issue_w = [&](int stage, int kc) {
    const int koff = kc * 64;
#pragma unroll
    for (int i = 0; i < 8; i++) {
      int idx = t + i * 256;
      int comp = idx >> 10;             // 0: Wh, 1: Wl
      int r = (idx >> 3) & 127;
      int c = idx & 7;
      const __half* src =
          (comp ? Wl : Wh) + (size_t)(n0 + r) * HID + koff + c * 8;
      uint32_t dst = sb + SW_BASE + stage * W_STG + comp * TILE_BYTES +
                     r * (RS * 2) + c * 16;
      CP_ASYNC16(dst, src);
    }
  };

  issue_w(0, 0);
  CP_COMMIT();

  float acc[4][4][4] = {};

  const int a_row = (l & 15);
  const int a_koff = ((l >> 4) & 1) * 16;
  const int b_row = (l & 7) + ((l >> 4) & 1) * 8;
  const int b_koff = ((l >> 3) & 1) * 16;

  for (int kc = 0; kc < 8; kc++) {
    const int koff = kc * 64;
    if constexpr (AFP32) {
      const float* Af = p.af[z];
#pragma unroll
      for (int i = 0; i < 8; i++) {     // 2048 float4 -> fp16 x4
        int v = t + i * 256;
        int row = v >> 4, c = v & 15;
        float4 fv = *(const float4*)(Af + (size_t)(m0 + row) * HID + koff +
                                     c * 4);
        uint2 ho;
        ho.x = pack_f16(fv.x, fv.y);
        ho.y = pack_f16(fv.z, fv.w);
        *(uint2*)(smem + SA16 + row * (RS * 2) + c * 8) = ho;
      }
    } else {
#pragma unroll
      for (int i = 0; i < 4; i++) {     // 1024 x 16B cp.async
        int idx = t + i * 256;
        int r = idx >> 3;
        int c = idx & 7;
        const __half* src = p.a16 + (size_t)(m0 + r) * HID + koff + c * 8;
        uint32_t dst = sb + SA16 + r * (RS * 2) + c * 16;
        CP_ASYNC16(dst, src);
      }
      CP_COMMIT();
    }
    if (kc + 1 < 8) {
      issue_w((kc + 1) & 1, kc + 1);
      CP_COMMIT();
      CP_WAIT1();
    } else {
      CP_WAIT0();
    }
    __syncthreads();
    const uint32_t st_w = sb + SW_BASE + (kc & 1) * W_STG;

#pragma unroll
    for (int ks = 0; ks < 4; ks++) {
      const int kb = ks * 32;
      uint32_t af[4][4], bh[8], bl[8];
#pragma unroll
      for (int mt = 0; mt < 4; mt++) {
        uint32_t ra = (wm * 64 + mt * 16 + a_row) * (RS * 2) + kb + a_koff;
        LDMX4(af[mt][0], af[mt][1], af[mt][2], af[mt][3], sb + SA16 + ra);
      }
#pragma unroll
      for (int np = 0; np < 2; np++) {
        uint32_t rb = (wn * 32 + np * 16 + b_row) * (RS * 2) + kb + b_koff;
        LDMX4(bh[np * 4 + 0], bh[np * 4 + 1], bh[np * 4 + 2], bh[np * 4 + 3],
              st_w + rb);
        LDMX4(bl[np * 4 + 0], bl[np * 4 + 1], bl[np * 4 + 2], bl[np * 4 + 3],
              st_w + TILE_BYTES + rb);
      }
#pragma unroll
      for (int mt = 0; mt < 4; mt++)
#pragma unroll
        for (int nt = 0; nt < 4; nt++) {
          float* c = acc[mt][nt];
          mma_f16(c[0], c[1], c[2], c[3], af[mt][0], af[mt][1], af[mt][2],
                  af[mt][3], bh[nt * 2], bh[nt * 2 + 1]);
          mma_f16(c[0], c[1], c[2], c[3], af[mt][0], af[mt][1], af[mt][2],
                  af[mt][3], bl[nt * 2], bl[nt * 2 + 1]);
        }
    }
    __syncthreads();
  }

  const int er = l >> 2, ec = (l & 3) * 2;
#pragma unroll
  for (int mt = 0; mt < 4; mt++) {
    int row = m0 + wm * 64 + mt * 16 + er;
#pragma unroll
    for (int nt = 0; nt < 4; nt++) {
      int col = n0 + wn * 32 + nt * 8 + ec;
      float* a = acc[mt][nt];
      if constexpr (F16OUT) {
        size_t i0 = (size_t)row * HID + col;
        size_t i1 = (size_t)(row + 8) * HID + col;
        *(uint32_t*)&p.c16[z][i0] = pack_f16(a[0], a[1]);
        *(uint32_t*)&p.c16[z][i1] = pack_f16(a[2], a[3]);
      } else {
        *(float2*)&p.c[(size_t)row * HID + col] = make_float2(a[0], a[1]);
        *(float2*)&p.c[(size_t)(row + 8) * HID + col] =
            make_float2(a[2], a[3]);
      }
    }
  }
}

// ---------------------------------------------------------------------------
// fp16 flash attention (single-term QK/PV, fp32 softmax, LPT batch order).
// exp2 computed via FMA-pipe polynomial (fexp2) — ~67M MUFU ops removed
// from a quarter-rate pipe whose busy time matched the tensor pipe's.
// ---------------------------------------------------------------------------
constexpr float SC2 = 0.125f * 1.4426950408889634f;  // (1/8)*log2(e)

constexpr int AQ16 = 0;                        // Q fp16: 128 x 144B
constexpr int ASTG0 = 128 * RS * 2;            // 18432
constexpr int AKV_COMP = 64 * RS * 2;          // 9216 (K or V per stage)
constexpr int ASTG_SZ = 2 * AKV_COMP;          // 18432
constexpr int ATTN_SMEM = ASTG0 + 2 * ASTG_SZ; // 55296

__global__ __launch_bounds__(256, 2) void attn_hmma(
    const __half* __restrict__ Q16, const __half* __restrict__ K16,
    const __half* __restrict__ V16, const int* __restrict__ valid_lens,
    __half* __restrict__ O16) {
  extern __shared__ __align__(128) char smem[];
  const uint32_t sb = smem_u32(smem);
  const int qt = blockIdx.x, h = blockIdx.y;
  const int t = threadIdx.x;
  const int wid = t >> 5, l = t & 31;
  const int q0 = qt * 128;

  // LPT: map z to the z-th largest-vlen batch (ties broken by index).
  int b = 0;
  {
    const int z = blockIdx.z;
    int v[4] = {valid_lens[0], valid_lens[1], valid_lens[2], valid_lens[3]};
#pragma unroll
    for (int i = 0; i < 4; i++) {
      int r = 0;
#pragma unroll
      for (int j = 0; j < 4; j++)
        r += (v[j] > v[i]) || (v[j] == v[i] && j < i);
      if (r == z) b = i;
    }
  }
  const int vlen = valid_lens[b];
  const int ntiles = (vlen + 63) >> 6;

  auto issue_tile = [&](int stage, int kbase) {
#pragma unroll
    for (int i = 0; i < 4; i++) {       // 1024 x 16B cp.async
      int idx = t + i * 256;
      int comp = idx >> 9;              // 0: K, 1: V
      int r = (idx >> 3) & 63;
      int c = idx & 7;
      const __half* src =
          (comp ? V16 : K16) + (size_t)(b * S + kbase + r) * HID + h * DH +
          c * 8;
      uint32_t dst = sb + ASTG0 + stage * ASTG_SZ + comp * AKV_COMP +
                     r * (RS * 2) + c * 16;
      CP_ASYNC16(dst, src);
    }
  };

  issue_tile(0, 0);
  CP_COMMIT();
#pragma unroll
  for (int i = 0; i < 4; i++) {         // Q tile: 1024 x 16B
    int v = t + i * 256;
    int row = v >> 3, c = v & 7;
    size_t g = (size_t)(b * S + q0 + row) * HID + h * DH + c * 8;
    *(uint4*)(smem + AQ16 + row * (RS * 2) + c * 16) =
        *(const uint4*)(Q16 + g);
  }
  __syncthreads();

  const int a_row = (l & 15);
  const int a_koff = ((l >> 4) & 1) * 16;
  const int b_row = (l & 7) + ((l >> 4) & 1) * 8;
  const int b_koff = ((l >> 3) & 1) * 16;
  const int v_row = (l & 7) + ((l >> 3) & 1) * 8;
  const int v_col = ((l >> 4) & 1) * 16;
  const int cb = (l & 3) * 2;

  uint32_t qf[4][4];
#pragma unroll
  for (int ks = 0; ks < 4; ks++) {
    uint32_t ra = (wid * 16 + a_row) * (RS * 2) + ks * 32 + a_koff;
    LDMX4(qf[ks][0], qf[ks][1], qf[ks][2], qf[ks][3], sb + AQ16 + ra);
  }

  float oacc[8][4] = {};
  float m0r = -1e30f, m1r = -1e30f, l0r = 0.f, l1r = 0.f;

  for (int kt = 0; kt < ntiles; kt++) {
    const int kbase = kt * 64;
    const uint32_t kb16 = sb + ASTG0 + (kt & 1) * ASTG_SZ;
    const uint32_t vb16 = kb16 + AKV_COMP;

    CP_WAIT0();
    __syncthreads();
    if (kt + 1 < ntiles) {
      issue_tile((kt + 1) & 1, kbase + 64);
      CP_COMMIT();
    }

    float sc[8][4];
#pragma unroll
    for (int nt = 0; nt < 8; nt++)
#pragma unroll
      for (int c = 0; c < 4; c++) sc[nt][c] = 0.f;
#pragma unroll
    for (int ks = 0; ks < 4; ks++) {
      uint32_t kf[16];
#pragma unroll
      for (int np = 0; np < 4; np++) {
        uint32_t rb = (np * 16 + b_row) * (RS * 2) + ks * 32 + b_koff;
        LDMX4(kf[np * 4 + 0], kf[np * 4 + 1], kf[np * 4 + 2], kf[np * 4 + 3],
              kb16 + rb);
      }
#pragma unroll
      for (int nt = 0; nt < 8; nt++) {
        float* c = sc[nt];
        mma_f16(c[0], c[1], c[2], c[3], qf[ks][0], qf[ks][1], qf[ks][2],
                qf[ks][3], kf[nt * 2], kf[nt * 2 + 1]);
      }
    }

#pragma unroll
    for (int nt = 0; nt < 8; nt++)
#pragma unroll
      for (int c = 0; c < 4; c++) sc[nt][c] *= SC2;
    if (kbase + 64 > vlen) {
#pragma unroll
      for (int nt = 0; nt < 8; nt++) {
        int k0 = kbase + nt * 8 + cb;
        if (k0 >= vlen) { sc[nt][0] = -1e30f; sc[nt][2] = -1e30f; }
        if (k0 + 1 >= vlen) { sc[nt][1] = -1e30f; sc[nt][3] = -1e30f; }
      }
    }

    float rm0 = -1e30f, rm1 = -1e30f;
#pragma unroll
    for (int nt = 0; nt < 8; nt++) {
      rm0 = fmaxf(rm0, fmaxf(sc[nt][0], sc[nt][1]));
      rm1 = fmaxf(rm1, fmaxf(sc[nt][2], sc[nt][3]));
    }
    rm0 = fmaxf(rm0, __shfl_xor_sync(0xffffffffu, rm0, 1));
    rm0 = fmaxf(rm0, __shfl_xor_sync(0xffffffffu, rm0, 2));
    rm1 = fmaxf(rm1, __shfl_xor_sync(0xffffffffu, rm1, 1));
    rm1 = fmaxf(rm1, __shfl_xor_sync(0xffffffffu, rm1, 2));
    float mn0 = fmaxf(m0r, rm0), mn1 = fmaxf(m1r, rm1);
    float corr0 = fexp2(m0r - mn0), corr1 = fexp2(m1r - mn1);

    uint32_t pf[8][2];
    float rs0 = 0.f, rs1 = 0.f;
#pragma unroll
    for (int nt = 0; nt < 8; nt++) {
      float p0 = fexp2(sc[nt][0] - mn0);
      float p1 = fexp2(sc[nt][1] - mn0);
      float p2 = fexp2(sc[nt][2] - mn1);
      float p3 = fexp2(sc[nt][3] - mn1);
      rs0 += p0 + p1;
      rs1 += p2 + p3;
      pf[nt][0] = pack_f16(p0, p1);
      pf[nt][1] = pack_f16(p2, p3);
    }
    rs0 += __shfl_xor_sync(0xffffffffu, rs0, 1);
    rs0 += __shfl_xor_sync(0xffffffffu, rs0, 2);
    rs1 += __shfl_xor_sync(0xffffffffu, rs1, 1);
    rs1 += __shfl_xor_sync(0xffffffffu, rs1, 2);
    l0r = l0r * corr0 + rs0;
    l1r = l1r * corr1 + rs1;
    m0r = mn0;
    m1r = mn1;
#pragma unroll
    for (int nt = 0; nt < 8; nt++) {
      oacc[nt][0] *= corr0;
      oacc[nt][1] *= corr0;
      oacc[nt][2] *= corr1;
      oacc[nt][3] *= corr1;
    }

#pragma unroll
    for (int ks = 0; ks < 4; ks++) {
      uint32_t vf[16];
#pragma unroll
      for (int np = 0; np < 4; np++) {
        uint32_t rv = (ks * 16 + v_row) * (RS * 2) + np * 32 + v_col;
        LDMX4T(vf[np * 4 + 0], vf[np * 4 + 1], vf[np * 4 + 2], vf[np * 4 + 3],
               vb16 + rv);
      }
      uint32_t a0 = pf[2 * ks][0], a1 = pf[2 * ks][1];
      uint32_t a2 = pf[2 * ks + 1][0], a3 = pf[2 * ks + 1][1];
#pragma unroll
      for (int nt = 0; nt < 8; nt++) {
        float* c = oacc[nt];
        mma_f16(c[0], c[1], c[2], c[3], a0, a1, a2, a3, vf[nt * 2],
                vf[nt * 2 + 1]);
      }
    }
  }

  float inv0 = 1.f / l0r, inv1 = 1.f / l1r;
  int r0 = q0 + wid * 16 + (l >> 2);
#pragma unroll
  for (int nt = 0; nt < 8; nt++) {
    int col = h * DH + nt * 8 + cb;
    size_t i0 = (size_t)(b * S + r0) * HID + col;
    size_t i1 = (size_t)(b * S + r0 + 8) * HID + col;
    *(uint32_t*)&O16[i0] = pack_f16(oacc[nt][0] * inv0, oacc[nt][1] * inv0);
    *(uint32_t*)&O16[i1] = pack_f16(oacc[nt][2] * inv1, oacc[nt][3] * inv1);
  }
}

// ---------------------------------------------------------------------------
extern "C" void kernel_launch(void* const* d_in, const int* in_sizes, int n_in,
                              void* d_out, int out_size) {
  const float* queries = (const float*)d_in[0];
  const float* keys    = (const float*)d_in[1];
  const float* values  = (const float*)d_in[2];
  const int*   vlens   = (const int*)d_in[3];
  const float* W[4]    = {(const float*)d_in[4], (const float*)d_in[5],
                          (const float*)d_in[6], (const float*)d_in[7]};
  float* out = (float*)d_out;

  __half *whb, *wlb, *q16, *k16, *v16, *o16;
  cudaGetSymbolAddress((void**)&whb, g_wh16);
  cudaGetSymbolAddress((void**)&wlb, g_wl16);
  cudaGetSymbolAddress((void**)&q16, g_q16);
  cudaGetSymbolAddress((void**)&k16, g_k16);
  cudaGetSymbolAddress((void**)&v16, g_v16);
  cudaGetSymbolAddress((void**)&o16, g_o16);
  const int WSZ = HID * HID;

  cudaFuncSetAttribute(gemm_tc_hmma<true, true>,
                       cudaFuncAttributeMaxDynamicSharedMemorySize, GEMM_SMEM);
  cudaFuncSetAttribute(gemm_tc_hmma<false, false>,
                       cudaFuncAttributeMaxDynamicSharedMemorySize, GEMM_SMEM);
  cudaFuncSetAttribute(attn_hmma,
                       cudaFuncAttributeMaxDynamicSharedMemorySize, ATTN_SMEM);

  // --- one batched weight split (Wq, Wk, Wv, Wo) -> fp16 hi/lo ---
  SplitBatch wsb = {};
  for (int i = 0; i < 4; i++) {
    wsb.src[i] = W[i];
    wsb.hi[i] = whb + i * WSZ;
    wsb.lo[i] = wlb + i * WSZ;
  }
  split_batch_kernel<<<dim3(WSZ / 4 / 256, 4), 256>>>(wsb, WSZ / 4);

  // --- Q/K/V projections (fp16x2), fp16 outputs; K/V vlen tiles skipped ---
  GemmBatch gp = {};
  gp.af[0] = queries; gp.af[1] = keys; gp.af[2] = values;
  for (int i = 0; i < 3; i++) {
    gp.wh[i] = whb + i * WSZ;
    gp.wl[i] = wlb + i * WSZ;
  }
  gp.c16[0] = q16; gp.c16[1] = k16; gp.c16[2] = v16;
  gp.vlens = vlens;
  gemm_tc_hmma<true, true>
      <<<dim3(HID / 128, M / 128, 3), 256, GEMM_SMEM>>>(gp);

  // --- attention (fp16 single-term, LPT batch order, FMA-pipe exp2) ---
  attn_hmma<<<dim3(S / 128, NH, B), 256, ATTN_SMEM>>>(q16, k16, v16, vlens,
                                                      o16);

  // --- output projection (fp16x2 on fp16 O, fp32 out) ---
  GemmBatch go = {};
  go.a16 = o16;
  go.wh[0] = whb + 3 * WSZ;
  go.wl[0] = wlb + 3 * WSZ;
  go.c = out;
  go.vlens = nullptr;
  gemm_tc_hmma<false, false>
      <<<dim3(HID / 128, M / 128, 1), 256, GEMM_SMEM>>>(go);
}

// round 17
// speedup vs baseline: 1.1495x; 1.1495x over previous
#include <cuda_runtime.h>
#include <cuda_bf16.h>
#include <cuda_fp16.h>
#include <cstdint>

// Problem constants
constexpr int B   = 4;
constexpr int S   = 2048;
constexpr int HID = 512;
constexpr int NH  = 8;
constexpr int DH  = 64;
constexpr int M   = B * S;       // 8192

// Scratch (device globals — no runtime allocation allowed)
__device__ __half g_wh16[4][HID * HID], g_wl16[4][HID * HID];
__device__ __half g_q16[M * HID], g_k16[M * HID], g_v16[M * HID];
__device__ __half g_o16[M * HID];

// ---------------------------------------------------------------------------
// mma.sync / ldmatrix / cp.async helpers (plain sm_80+ PTX)
// ---------------------------------------------------------------------------
__device__ __forceinline__ uint32_t smem_u32(const void* p) {
  uint32_t a;
  asm("{ .reg .u64 t; cvta.to.shared.u64 t, %1; cvt.u32.u64 %0, t; }"
      : "=r"(a) : "l"(p));
  return a;
}

#define LDMX4(r0, r1, r2, r3, addr)                                       \
  asm volatile(                                                           \
      "ldmatrix.sync.aligned.m8n8.x4.shared.b16 {%0,%1,%2,%3}, [%4];"     \
      : "=r"(r0), "=r"(r1), "=r"(r2), "=r"(r3) : "r"(addr))

#define LDMX4T(r0, r1, r2, r3, addr)                                      \
  asm volatile(                                                           \
      "ldmatrix.sync.aligned.m8n8.x4.trans.shared.b16 {%0,%1,%2,%3}, [%4];" \
      : "=r"(r0), "=r"(r1), "=r"(r2), "=r"(r3) : "r"(addr))

#define CP_ASYNC16(dst, src)                                              \
  asm volatile("cp.async.cg.shared.global [%0], [%1], 16;" ::             \
                   "r"(dst), "l"(src))
#define CP_COMMIT() asm volatile("cp.async.commit_group;" ::: "memory")
#define CP_WAIT0() asm volatile("cp.async.wait_group 0;" ::: "memory")
#define CP_WAIT1() asm volatile("cp.async.wait_group 1;" ::: "memory")

__device__ __forceinline__ void mma_f16(float& c0, float& c1, float& c2,
                                        float& c3, uint32_t a0, uint32_t a1,
                                        uint32_t a2, uint32_t a3,
                                        uint32_t b0, uint32_t b1) {
  asm volatile(
      "mma.sync.aligned.m16n8k16.row.col.f32.f16.f16.f32 "
      "{%0,%1,%2,%3}, {%4,%5,%6,%7}, {%8,%9}, {%0,%1,%2,%3};"
      : "+f"(c0), "+f"(c1), "+f"(c2), "+f"(c3)
      : "r"(a0), "r"(a1), "r"(a2), "r"(a3), "r"(b0), "r"(b1));
}

__device__ __forceinline__ uint32_t pack_f16(float a, float b) {
  __half2 t = __floats2half2_rn(a, b);
  return *(uint32_t*)&t;
}

// ---------------------------------------------------------------------------
// Weight split: fp32 -> fp16 hi + fp16 lo (2-term; residual ~2^-22).
// ---------------------------------------------------------------------------
struct SplitBatch {
  const float* src[4];
  __half* hi[4];
  __half* lo[4];
};

__global__ __launch_bounds__(256) void split_batch_kernel(SplitBatch sb,
                                                          int n4) {
  int i = blockIdx.x * blockDim.x + threadIdx.x;
  if (i >= n4) return;
  int z = blockIdx.y;
  float4 v = ((const float4*)sb.src[z])[i];
  float hx = __half2float(__float2half_rn(v.x));
  float hy = __half2float(__float2half_rn(v.y));
  float hz = __half2float(__float2half_rn(v.z));
  float hw = __half2float(__float2half_rn(v.w));
  uint2 ho, lw;
  ho.x = pack_f16(v.x, v.y);
  ho.y = pack_f16(v.z, v.w);
  lw.x = pack_f16(v.x - hx, v.y - hy);
  lw.y = pack_f16(v.z - hz, v.w - hw);
  ((uint2*)sb.hi[z])[i] = ho;
  ((uint2*)sb.lo[z])[i] = lw;
}

// ---------------------------------------------------------------------------
// HMMA fp16x2 GEMM-NT: C = A16 @ (Wh + Wl)^T — 2 MMA terms per k16.
// A: AFP32 -> fused fp32->fp16 conversion (single stage);
//    else   -> cp.async DOUBLE-BUFFERED (out-proj's A latency was exposed:
//    it was issued then immediately completed by CP_WAIT1 each chunk).
// W: fp16 hi/lo, cp.async double-buffered.
// Total smem 110.6 KB -> 2 CTAs/SM still fit.
// ---------------------------------------------------------------------------
constexpr int RS = 72;                    // smem row stride in halfs (144 B)
constexpr int TILE_BYTES = 128 * RS * 2;  // 18432 per tile
constexpr int SA16 = 0;                   // A: 2 stages x 1 tile
constexpr int SW_BASE = 2 * TILE_BYTES;   // 36864
constexpr int W_STG = 2 * TILE_BYTES;     // Wh+Wl per stage
constexpr int GEMM_SMEM = SW_BASE + 2 * W_STG;  // 110592

struct GemmBatch {
  const float* af[3];                 // AFP32 inputs
  const __half* a16;                  // !AFP32 input (out-proj A = O fp16)
  const __half* wh[3];
  const __half* wl[3];
  __half* c16[3];                     // F16OUT outputs
  float* c;                           // !F16OUT output
  const int* vlens;                   // valid_lens (skip for z=1,2); null ok
};

template <bool AFP32, bool F16OUT>
__global__ __launch_bounds__(256, 2) void gemm_tc_hmma(GemmBatch p) {
  extern __shared__ __align__(128) char smem[];
  const uint32_t sb = smem_u32(smem);
  const int t = threadIdx.x;
  const int wid = t >> 5, l = t & 31;
  const int wm = wid >> 2;
  const int wn = wid & 3;
  const int m0 = blockIdx.y * 128;
  const int n0 = blockIdx.x * 128;
  const int z = blockIdx.z;

  if (AFP32 && z != 0) {
    int vl = p.vlens[m0 >> 11];       // batch = m0 / S (S = 2048)
    if ((m0 & (S - 1)) >= vl) return;
  }

  const __half* Wh = p.wh[z];
  const __half* Wl = p.wl[z];

  auto issue_w = [&](int stage, int kc) {
    const int koff = kc * 64;
#pragma unroll
    for (int i = 0; i < 8; i++) {
      int idx = t + i * 256;
      int comp = idx >> 10;             // 0: Wh, 1: Wl
      int r = (idx >> 3) & 127;
      int c = idx & 7;
      const __half* src =
          (comp ? Wl : Wh) + (size_t)(n0 + r) * HID + koff + c * 8;
      uint32_t dst = sb + SW_BASE + stage * W_STG + comp * TILE_BYTES +
                     r * (RS * 2) + c * 16;
      CP_ASYNC16(dst, src);
    }
  };

  auto issue_a16 = [&](int stage, int kc) {
    const int koff = kc * 64;
#pragma unroll
    for (int i = 0; i < 4; i++) {       // 1024 x 16B cp.async
      int idx = t + i * 256;
      int r = idx >> 3;
      int c = idx & 7;
      const __half* src = p.a16 + (size_t)(m0 + r) * HID + koff + c * 8;
      uint32_t dst = sb + SA16 + stage * TILE_BYTES + r * (RS * 2) + c * 16;
      CP_ASYNC16(dst, src);
    }
  };

  // prologue: chunk 0 (A for !AFP32 path joins W's commit group)
  if constexpr (!AFP32) issue_a16(0, 0);
  issue_w(0, 0);
  CP_COMMIT();

  float acc[4][4][4] = {};

  const int a_row = (l & 15);
  const int a_koff = ((l >> 4) & 1) * 16;
  const int b_row = (l & 7) + ((l >> 4) & 1) * 8;
  const int b_koff = ((l >> 3) & 1) * 16;

  for (int kc = 0; kc < 8; kc++) {
    const int koff = kc * 64;
    if constexpr (AFP32) {
      const float* Af = p.af[z];
#pragma unroll
      for (int i = 0; i < 8; i++) {     // 2048 float4 -> fp16 x4 (stage 0)
        int v = t + i * 256;
        int row = v >> 4, c = v & 15;
        float4 fv = *(const float4*)(Af + (size_t)(m0 + row) * HID + koff +
                                     c * 4);
        uint2 ho;
        ho.x = pack_f16(fv.x, fv.y);
        ho.y = pack_f16(fv.z, fv.w);
        *(uint2*)(smem + SA16 + row * (RS * 2) + c * 8) = ho;
      }
    }
    if (kc + 1 < 8) {
      if constexpr (!AFP32) issue_a16((kc + 1) & 1, kc + 1);
      issue_w((kc + 1) & 1, kc + 1);
      CP_COMMIT();
      CP_WAIT1();
    } else {
      CP_WAIT0();
    }
    __syncthreads();
    const uint32_t st_w = sb + SW_BASE + (kc & 1) * W_STG;
    const uint32_t st_a = sb + SA16 + (AFP32 ? 0 : (kc & 1) * TILE_BYTES);

#pragma unroll
    for (int ks = 0; ks < 4; ks++) {
      const int kb = ks * 32;
      uint32_t af[4][4], bh[8], bl[8];
#pragma unroll
      for (int mt = 0; mt < 4; mt++) {
        uint32_t ra = (wm * 64 + mt * 16 + a_row) * (RS * 2) + kb + a_koff;
        LDMX4(af[mt][0], af[mt][1], af[mt][2], af[mt][3], st_a + ra);
      }
#pragma unroll
      for (int np = 0; np < 2; np++) {
        uint32_t rb = (wn * 32 + np * 16 + b_row) * (RS * 2) + kb + b_koff;
        LDMX4(bh[np * 4 + 0], bh[np * 4 + 1], bh[np * 4 + 2], bh[np * 4 + 3],
              st_w + rb);
        LDMX4(bl[np * 4 + 0], bl[np * 4 + 1], bl[np * 4 + 2], bl[np * 4 + 3],
              st_w + TILE_BYTES + rb);
      }
#pragma unroll
      for (int mt = 0; mt < 4; mt++)
#pragma unroll
        for (int nt = 0; nt < 4; nt++) {
          float* c = acc[mt][nt];
          mma_f16(c[0], c[1], c[2], c[3], af[mt][0], af[mt][1], af[mt][2],
                  af[mt][3], bh[nt * 2], bh[nt * 2 + 1]);
          mma_f16(c[0], c[1], c[2], c[3], af[mt][0], af[mt][1], af[mt][2],
                  af[mt][3], bl[nt * 2], bl[nt * 2 + 1]);
        }
    }
    __syncthreads();
  }

  const int er = l >> 2, ec = (l & 3) * 2;
#pragma unroll
  for (int mt = 0; mt < 4; mt++) {
    int row = m0 + wm * 64 + mt * 16 + er;
#pragma unroll
    for (int nt = 0; nt < 4; nt++) {
      int col = n0 + wn * 32 + nt * 8 + ec;
      float* a = acc[mt][nt];
      if constexpr (F16OUT) {
        size_t i0 = (size_t)row * HID + col;
        size_t i1 = (size_t)(row + 8) * HID + col;
        *(uint32_t*)&p.c16[z][i0] = pack_f16(a[0], a[1]);
        *(uint32_t*)&p.c16[z][i1] = pack_f16(a[2], a[3]);
      } else {
        *(float2*)&p.c[(size_t)row * HID + col] = make_float2(a[0], a[1]);
        *(float2*)&p.c[(size_t)(row + 8) * HID + col] =
            make_float2(a[2], a[3]);
      }
    }
  }
}

// ---------------------------------------------------------------------------
// fp16 flash attention (single-term QK/PV, fp32 exp2f softmax, LPT batch
// order). Round-15 structure exactly — the round-16 FMA-polynomial exp2
// regressed (MUFU occupancy was hidden; the poly serialized the issue stream).
// ---------------------------------------------------------------------------
constexpr float SC2 = 0.125f * 1.4426950408889634f;  // (1/8)*log2(e)

constexpr int AQ16 = 0;                        // Q fp16: 128 x 144B
constexpr int ASTG0 = 128 * RS * 2;            // 18432
constexpr int AKV_COMP = 64 * RS * 2;          // 9216 (K or V per stage)
constexpr int ASTG_SZ = 2 * AKV_COMP;          // 18432
constexpr int ATTN_SMEM = ASTG0 + 2 * ASTG_SZ; // 55296

__global__ __launch_bounds__(256, 2) void attn_hmma(
    const __half* __restrict__ Q16, const __half* __restrict__ K16,
    const __half* __restrict__ V16, const int* __restrict__ valid_lens,
    __half* __restrict__ O16) {
  extern __shared__ __align__(128) char smem[];
  const uint32_t sb = smem_u32(smem);
  const int qt = blockIdx.x, h = blockIdx.y;
  const int t = threadIdx.x;
  const int wid = t >> 5, l = t & 31;
  const int q0 = qt * 128;

  // LPT: map z to the z-th largest-vlen batch (ties broken by index).
  int b = 0;
  {
    const int z = blockIdx.z;
    int v[4] = {valid_lens[0], valid_lens[1], valid_lens[2], valid_lens[3]};
#pragma unroll
    for (int i = 0; i < 4; i++) {
      int r = 0;
#pragma unroll
      for (int j = 0; j < 4; j++)
        r += (v[j] > v[i]) || (v[j] == v[i] && j < i);
      if (r == z) b = i;
    }
  }
  const int vlen = valid_lens[b];
  const int ntiles = (vlen + 63) >> 6;

  auto issue_tile = [&](int stage, int kbase) {
#pragma unroll
    for (int i = 0; i < 4; i++) {       // 1024 x 16B cp.async
      int idx = t + i * 256;
      int comp = idx >> 9;              // 0: K, 1: V
      int r = (idx >> 3) & 63;
      int c = idx & 7;
      const __half* src =
          (comp ? V16 : K16) + (size_t)(b * S + kbase + r) * HID + h * DH +
          c * 8;
      uint32_t dst = sb + ASTG0 + stage * ASTG_SZ + comp * AKV_COMP +
                     r * (RS * 2) + c * 16;
      CP_ASYNC16(dst, src);
    }
  };

  issue_tile(0, 0);
  CP_COMMIT();
#pragma unroll
  for (int i = 0; i < 4; i++) {         // Q tile: 1024 x 16B
    int v = t + i * 256;
    int row = v >> 3, c = v & 7;
    size_t g = (size_t)(b * S + q0 + row) * HID + h * DH + c * 8;
    *(uint4*)(smem + AQ16 + row * (RS * 2) + c * 16) =
        *(const uint4*)(Q16 + g);
  }
  __syncthreads();

  const int a_row = (l & 15);
  const int a_koff = ((l >> 4) & 1) * 16;
  const int b_row = (l & 7) + ((l >> 4) & 1) * 8;
  const int b_koff = ((l >> 3) & 1) * 16;
  const int v_row = (l & 7) + ((l >> 3) & 1) * 8;
  const int v_col = ((l >> 4) & 1) * 16;
  const int cb = (l & 3) * 2;

  uint32_t qf[4][4];
#pragma unroll
  for (int ks = 0; ks < 4; ks++) {
    uint32_t ra = (wid * 16 + a_row) * (RS * 2) + ks * 32 + a_koff;
    LDMX4(qf[ks][0], qf[ks][1], qf[ks][2], qf[ks][3], sb + AQ16 + ra);
  }

  float oacc[8][4] = {};
  float m0r = -1e30f, m1r = -1e30f, l0r = 0.f, l1r = 0.f;

  for (int kt = 0; kt < ntiles; kt++) {
    const int kbase = kt * 64;
    const uint32_t kb16 = sb + ASTG0 + (kt & 1) * ASTG_SZ;
    const uint32_t vb16 = kb16 + AKV_COMP;

    CP_WAIT0();
    __syncthreads();
    if (kt + 1 < ntiles) {
      issue_tile((kt + 1) & 1, kbase + 64);
      CP_COMMIT();
    }

    float sc[8][4];
#pragma unroll
    for (int nt = 0; nt < 8; nt++)
#pragma unroll
      for (int c = 0; c < 4; c++) sc[nt][c] = 0.f;
#pragma unroll
    for (int ks = 0; ks < 4; ks++) {
      uint32_t kf[16];
#pragma unroll
      for (int np = 0; np < 4; np++) {
        uint32_t rb = (np * 16 + b_row) * (RS * 2) + ks * 32 + b_koff;
        LDMX4(kf[np * 4 + 0], kf[np * 4 + 1], kf[np * 4 + 2], kf[np * 4 + 3],
              kb16 + rb);
      }
#pragma unroll
      for (int nt = 0; nt < 8; nt++) {
        float* c = sc[nt];
        mma_f16(c[0], c[1], c[2], c[3], qf[ks][0], qf[ks][1], qf[ks][2],
                qf[ks][3], kf[nt * 2], kf[nt * 2 + 1]);
      }
    }

#pragma unroll
    for (int nt = 0; nt < 8; nt++)
#pragma unroll
      for (int c = 0; c < 4; c++) sc[nt][c] *= SC2;
    if (kbase + 64 > vlen) {
#pragma unroll
      for (int nt = 0; nt < 8; nt++) {
        int k0 = kbase + nt * 8 + cb;
        if (k0 >= vlen) { sc[nt][0] = -1e30f; sc[nt][2] = -1e30f; }
        if (k0 + 1 >= vlen) { sc[nt][1] = -1e30f; sc[nt][3] = -1e30f; }
      }
    }

    float rm0 = -1e30f, rm1 = -1e30f;
#pragma unroll
    for (int nt = 0; nt < 8; nt++) {
      rm0 = fmaxf(rm0, fmaxf(sc[nt][0], sc[nt][1]));
      rm1 = fmaxf(rm1, fmaxf(sc[nt][2], sc[nt][3]));
    }
    rm0 = fmaxf(rm0, __shfl_xor_sync(0xffffffffu, rm0, 1));
    rm0 = fmaxf(rm0, __shfl_xor_sync(0xffffffffu, rm0, 2));
    rm1 = fmaxf(rm1, __shfl_xor_sync(0xffffffffu, rm1, 1));
    rm1 = fmaxf(rm1, __shfl_xor_sync(0xffffffffu, rm1, 2));
    float mn0 = fmaxf(m0r, rm0), mn1 = fmaxf(m1r, rm1);
    float corr0 = exp2f(m0r - mn0), corr1 = exp2f(m1r - mn1);

    uint32_t pf[8][2];
    float rs0 = 0.f, rs1 = 0.f;
#pragma unroll
    for (int nt = 0; nt < 8; nt++) {
      float p0 = exp2f(sc[nt][0] - mn0);
      float p1 = exp2f(sc[nt][1] - mn0);
      float p2 = exp2f(sc[nt][2] - mn1);
      float p3 = exp2f(sc[nt][3] - mn1);
      rs0 += p0 + p1;
      rs1 += p2 + p3;
      pf[nt][0] = pack_f16(p0, p1);
      pf[nt][1] = pack_f16(p2, p3);
    }
    rs0 += __shfl_xor_sync(0xffffffffu, rs0, 1);
    rs0 += __shfl_xor_sync(0xffffffffu, rs0, 2);
    rs1 += __shfl_xor_sync(0xffffffffu, rs1, 1);
    rs1 += __shfl_xor_sync(0xffffffffu, rs1, 2);
    l0r = l0r * corr0 + rs0;
    l1r = l1r * corr1 + rs1;
    m0r = mn0;
    m1r = mn1;
#pragma unroll
    for (int nt = 0; nt < 8; nt++) {
      oacc[nt][0] *= corr0;
      oacc[nt][1] *= corr0;
      oacc[nt][2] *= corr1;
      oacc[nt][3] *= corr1;
    }

#pragma unroll
    for (int ks = 0; ks < 4; ks++) {
      uint32_t vf[16];
#pragma unroll
      for (int np = 0; np < 4; np++) {
        uint32_t rv = (ks * 16 + v_row) * (RS * 2) + np * 32 + v_col;
        LDMX4T(vf[np * 4 + 0], vf[np * 4 + 1], vf[np * 4 + 2], vf[np * 4 + 3],
               vb16 + rv);
      }
      uint32_t a0 = pf[2 * ks][0], a1 = pf[2 * ks][1];
      uint32_t a2 = pf[2 * ks + 1][0], a3 = pf[2 * ks + 1][1];
#pragma unroll
      for (int nt = 0; nt < 8; nt++) {
        float* c = oacc[nt];
        mma_f16(c[0], c[1], c[2], c[3], a0, a1, a2, a3, vf[nt * 2],
                vf[nt * 2 + 1]);
      }
    }
  }

  float inv0 = 1.f / l0r, inv1 = 1.f / l1r;
  int r0 = q0 + wid * 16 + (l >> 2);
#pragma unroll
  for (int nt = 0; nt < 8; nt++) {
    int col = h * DH + nt * 8 + cb;
    size_t i0 = (size_t)(b * S + r0) * HID + col;
    size_t i1 = (size_t)(b * S + r0 + 8) * HID + col;
    *(uint32_t*)&O16[i0] = pack_f16(oacc[nt][0] * inv0, oacc[nt][1] * inv0);
    *(uint32_t*)&O16[i1] = pack_f16(oacc[nt][2] * inv1, oacc[nt][3] * inv1);
  }
}

// ---------------------------------------------------------------------------
extern "C" void kernel_launch(void* const* d_in, const int* in_sizes, int n_in,
                              void* d_out, int out_size) {
  const float* queries = (const float*)d_in[0];
  const float* keys    = (const float*)d_in[1];
  const float* values  = (const float*)d_in[2];
  const int*   vlens   = (const int*)d_in[3];
  const float* W[4]    = {(const float*)d_in[4], (const float*)d_in[5],
                          (const float*)d_in[6], (const float*)d_in[7]};
  float* out = (float*)d_out;

  __half *whb, *wlb, *q16, *k16, *v16, *o16;
  cudaGetSymbolAddress((void**)&whb, g_wh16);
  cudaGetSymbolAddress((void**)&wlb, g_wl16);
  cudaGetSymbolAddress((void**)&q16, g_q16);
  cudaGetSymbolAddress((void**)&k16, g_k16);
  cudaGetSymbolAddress((void**)&v16, g_v16);
  cudaGetSymbolAddress((void**)&o16, g_o16);
  const int WSZ = HID * HID;

  cudaFuncSetAttribute(gemm_tc_hmma<true, true>,
                       cudaFuncAttributeMaxDynamicSharedMemorySize, GEMM_SMEM);
  cudaFuncSetAttribute(gemm_tc_hmma<false, false>,
                       cudaFuncAttributeMaxDynamicSharedMemorySize, GEMM_SMEM);
  cudaFuncSetAttribute(attn_hmma,
                       cudaFuncAttributeMaxDynamicSharedMemorySize, ATTN_SMEM);

  // --- one batched weight split (Wq, Wk, Wv, Wo) -> fp16 hi/lo ---
  SplitBatch wsb = {};
  for (int i = 0; i < 4; i++) {
    wsb.src[i] = W[i];
    wsb.hi[i] = whb + i * WSZ;
    wsb.lo[i] = wlb + i * WSZ;
  }
  split_batch_kernel<<<dim3(WSZ / 4 / 256, 4), 256>>>(wsb, WSZ / 4);

  // --- Q/K/V projections (fp16x2), fp16 outputs; K/V vlen tiles skipped ---
  GemmBatch gp = {};
  gp.af[0] = queries; gp.af[1] = keys; gp.af[2] = values;
  for (int i = 0; i < 3; i++) {
    gp.wh[i] = whb + i * WSZ;
    gp.wl[i] = wlb + i * WSZ;
  }
  gp.c16[0] = q16; gp.c16[1] = k16; gp.c16[2] = v16;
  gp.vlens = vlens;
  gemm_tc_hmma<true, true>
      <<<dim3(HID / 128, M / 128, 3), 256, GEMM_SMEM>>>(gp);

  // --- attention (fp16 single-term, LPT batch order, exp2f softmax) ---
  attn_hmma<<<dim3(S / 128, NH, B), 256, ATTN_SMEM>>>(q16, k16, v16, vlens,
                                                      o16);

  // --- output projection (fp16x2, A double-buffered, fp32 out) ---
  GemmBatch go = {};
  go.a16 = o16;
  go.wh[0] = whb + 3 * WSZ;
  go.wl[0] = wlb + 3 * WSZ;
  go.c = out;
  go.vlens = nullptr;
  gemm_tc_hmma<false, false>
      <<<dim3(HID / 128, M / 128, 1), 256, GEMM_SMEM>>>(go);
}